// round 6
// baseline (speedup 1.0000x reference)
#include <cuda_runtime.h>
#include <cuda_bf16.h>
#include <cstdint>

// ---------------------------------------------------------------------------
// image_prj: D = dct2(image) [2048x2048, ortho] -> pad to 2198x2198 ->
// 32-angle radon (bilinear, WRAP) -> lines^T / max
// GEMMs: mma.sync bf16x3 split (tensor-pipe ceiling ~64%).
// Radon: smem-tiled gather with ANGLE-ADAPTIVE row stride (bank-conflict-free).
// ---------------------------------------------------------------------------

#define MM    2048
#define PP    2198
#define PADB  75
#define NANG  32
#define TOT   (NANG * PP)
#define NYT   35
#define NXT   35

__device__ __nv_bfloat16 g_Ch[MM * MM], g_Cl[MM * MM];
__device__ __nv_bfloat16 g_XTh[MM * MM], g_XTl[MM * MM];
__device__ __nv_bfloat16 g_Th[MM * MM], g_Tl[MM * MM];
__device__ float    g_pad[PP * PP];
__device__ float    g_lpart[NYT * TOT];
__device__ float    g_lines[TOT];
__device__ unsigned g_maxbits;

// ------------------------------ PTX helpers -------------------------------
__device__ __forceinline__ uint32_t smem_u32(const void* p) {
    uint32_t a;
    asm("{ .reg .u64 t; cvta.to.shared.u64 t, %1; cvt.u32.u64 %0, t; }"
        : "=r"(a) : "l"(p));
    return a;
}
#define CP_COMMIT() asm volatile("cp.async.commit_group;" ::: "memory")
#define CP_WAIT(n)  asm volatile("cp.async.wait_group %0;" :: "n"(n) : "memory")

__device__ __forceinline__ void cp16(uint32_t dst, const void* src) {
    asm volatile("cp.async.cg.shared.global [%0], [%1], 16;"
                 :: "r"(dst), "l"(src) : "memory");
}
__device__ __forceinline__ void ldsm4(uint32_t& r0, uint32_t& r1,
                                      uint32_t& r2, uint32_t& r3, uint32_t a) {
    asm volatile("ldmatrix.sync.aligned.m8n8.x4.shared.b16 {%0,%1,%2,%3}, [%4];"
                 : "=r"(r0), "=r"(r1), "=r"(r2), "=r"(r3) : "r"(a));
}
__device__ __forceinline__ void mma16816(float* d, const uint32_t* a,
                                         const uint32_t* b) {
    asm volatile("mma.sync.aligned.m16n8k16.row.col.f32.bf16.bf16.f32 "
                 "{%0,%1,%2,%3}, {%4,%5,%6,%7}, {%8,%9}, {%0,%1,%2,%3};"
                 : "+f"(d[0]), "+f"(d[1]), "+f"(d[2]), "+f"(d[3])
                 : "r"(a[0]), "r"(a[1]), "r"(a[2]), "r"(a[3]),
                   "r"(b[0]), "r"(b[1]));
}
__device__ __forceinline__ uint32_t sw128(uint32_t b) { return b ^ ((b >> 3) & 0x70); }

// --------------------------- small prep kernels ---------------------------
__global__ void init_kernel() {
    int idx = blockIdx.x * 256 + threadIdx.x;
    if (idx < PP * PP) g_pad[idx] = 0.0f;
    if (idx == 0) g_maxbits = 0u;
}

__global__ void gen_dct_kernel() {
    int idx = blockIdx.x * 256 + threadIdx.x;
    if (idx >= MM * MM) return;
    int k = idx >> 11;
    int n = idx & (MM - 1);
    int r = ((2 * n + 1) * k) & (4 * MM - 1);
    float t = (float)r * (1.0f / (2.0f * MM));
    float c = cospif(t);
    float s = (k == 0) ? 0.022097086912079608f : 0.03125f;
    float v = s * c;
    __nv_bfloat16 h = __float2bfloat16(v);
    g_Ch[idx] = h;
    g_Cl[idx] = __float2bfloat16(v - __bfloat162float(h));
}

__global__ void transpose_split_kernel(const float* __restrict__ img) {
    __shared__ float tile[32][33];
    int bx = blockIdx.x * 32, by = blockIdx.y * 32;
    int tx = threadIdx.x, ty = threadIdx.y;
#pragma unroll
    for (int i = 0; i < 4; i++)
        tile[ty + i * 8][tx] = img[(size_t)(by + ty + i * 8) * MM + bx + tx];
    __syncthreads();
#pragma unroll
    for (int i = 0; i < 4; i++) {
        float v = tile[tx][ty + i * 8];
        __nv_bfloat16 h = __float2bfloat16(v);
        size_t o = (size_t)(bx + ty + i * 8) * MM + by + tx;
        g_XTh[o] = h;
        g_XTl[o] = __float2bfloat16(v - __bfloat162float(h));
    }
}

// ------------------------------ HMMA GEMM ---------------------------------
#define KC      64
#define NCH     (MM / KC)
#define TA      32768
#define TB      16384
#define ST_SZ   (2 * TA + 2 * TB)
#define STAGES  2
#define SM_GEMM (STAGES * ST_SZ)

__device__ __forceinline__ void load_chunk(
    uint32_t st,
    const __nv_bfloat16* __restrict__ Ah, const __nv_bfloat16* __restrict__ Al,
    const __nv_bfloat16* __restrict__ Bh, const __nv_bfloat16* __restrict__ Bl,
    int m0, int n0, int k0, int tid)
{
#pragma unroll
    for (int t = 0; t < 24; ++t) {
        int idx = tid + t * 256;
        if (idx < 4096) {
            int sp  = idx >> 11;
            int r   = (idx >> 3) & 255;
            int seg = idx & 7;
            const __nv_bfloat16* src = sp ? Al : Ah;
            cp16(st + sp * TA + sw128(r * 128 + seg * 16),
                 src + (size_t)(m0 + r) * MM + k0 + seg * 8);
        } else {
            int j   = idx - 4096;
            int sp  = j >> 10;
            int r   = (j >> 3) & 127;
            int seg = j & 7;
            const __nv_bfloat16* src = sp ? Bl : Bh;
            cp16(st + 2 * TA + sp * TB + sw128(r * 128 + seg * 16),
                 src + (size_t)(n0 + r) * MM + k0 + seg * 8);
        }
    }
}

template <int WRITEMODE>
__global__ __launch_bounds__(256, 1) void gemm_hmma_kernel(
    const __nv_bfloat16* __restrict__ Ah, const __nv_bfloat16* __restrict__ Al,
    const __nv_bfloat16* __restrict__ Bh, const __nv_bfloat16* __restrict__ Bl,
    float* __restrict__ outF, __nv_bfloat16* __restrict__ outH,
    __nv_bfloat16* __restrict__ outL)
{
    extern __shared__ char smem[];
    uint32_t sb = smem_u32(smem);
    int tid = threadIdx.x, wid = tid >> 5, lane = tid & 31;
    int m0 = blockIdx.y * 256, n0 = blockIdx.x * 128;
    int wm = wid >> 1, wn = wid & 1;

    float acc[4][8][4];
#pragma unroll
    for (int i = 0; i < 4; i++)
#pragma unroll
        for (int j = 0; j < 8; j++)
#pragma unroll
            for (int q = 0; q < 4; q++) acc[i][j][q] = 0.0f;

    int aRow  = wm * 64 + (lane & 7) + ((lane >> 3) & 1) * 8;
    int aSegB = lane >> 4;
    uint32_t aXor  = (uint32_t)(aRow & 7) << 4;
    uint32_t aBase = (uint32_t)aRow * 128;
    int bRow  = wn * 64 + (lane & 7) + ((lane >> 4) & 1) * 8;
    int bSegB = (lane >> 3) & 1;
    uint32_t bXor  = (uint32_t)(bRow & 7) << 4;
    uint32_t bBase = (uint32_t)bRow * 128;

    load_chunk(sb + 0 * ST_SZ, Ah, Al, Bh, Bl, m0, n0, 0 * KC, tid); CP_COMMIT();
    load_chunk(sb + 1 * ST_SZ, Ah, Al, Bh, Bl, m0, n0, 1 * KC, tid); CP_COMMIT();

    for (int c = 0; c < NCH; ++c) {
        if (c + 1 < NCH) CP_WAIT(1);
        else             CP_WAIT(0);
        __syncthreads();

        uint32_t st = sb + (c & 1) * ST_SZ;
        uint32_t sAh = st, sAl = st + TA, sBh = st + 2 * TA, sBl = st + 2 * TA + TB;

#pragma unroll
        for (int ks = 0; ks < 4; ++ks) {
            uint32_t aSegOff = (uint32_t)(((ks * 2 + aSegB) * 16) ^ aXor);
            uint32_t bSegOff = (uint32_t)(((ks * 2 + bSegB) * 16) ^ bXor);
            uint32_t bh[4][4], bl[4][4];
#pragma unroll
            for (int p = 0; p < 4; ++p) {
                uint32_t off = bBase + p * 2048 + bSegOff;
                ldsm4(bh[p][0], bh[p][1], bh[p][2], bh[p][3], sBh + off);
                ldsm4(bl[p][0], bl[p][1], bl[p][2], bl[p][3], sBl + off);
            }
#pragma unroll
            for (int mt = 0; mt < 4; ++mt) {
                uint32_t ah[4], al[4];
                uint32_t off = aBase + mt * 2048 + aSegOff;
                ldsm4(ah[0], ah[1], ah[2], ah[3], sAh + off);
                ldsm4(al[0], al[1], al[2], al[3], sAl + off);
#pragma unroll
                for (int nt = 0; nt < 8; ++nt) {
                    const uint32_t* pbh = &bh[nt >> 1][(nt & 1) * 2];
                    const uint32_t* pbl = &bl[nt >> 1][(nt & 1) * 2];
                    mma16816(acc[mt][nt], ah, pbh);
                    mma16816(acc[mt][nt], ah, pbl);
                    mma16816(acc[mt][nt], al, pbh);
                }
            }
        }
        __syncthreads();
        if (c + 2 < NCH)
            load_chunk(sb + (c & 1) * ST_SZ, Ah, Al, Bh, Bl,
                       m0, n0, (c + 2) * KC, tid);
        CP_COMMIT();
    }

#pragma unroll
    for (int mt = 0; mt < 4; ++mt)
#pragma unroll
        for (int nt = 0; nt < 8; ++nt) {
#pragma unroll
            for (int h = 0; h < 2; ++h) {
                int row = m0 + wm * 64 + mt * 16 + (lane >> 2) + h * 8;
                int col = n0 + wn * 64 + nt * 8 + (lane & 3) * 2;
                float v0 = acc[mt][nt][h * 2 + 0];
                float v1 = acc[mt][nt][h * 2 + 1];
                if (WRITEMODE == 0) {
                    size_t o = (size_t)(row + PADB) * PP + col + PADB;
                    outF[o]     = v0;
                    outF[o + 1] = v1;
                } else {
                    __nv_bfloat16 h0 = __float2bfloat16(v0);
                    __nv_bfloat16 h1 = __float2bfloat16(v1);
                    __nv_bfloat16 l0 = __float2bfloat16(v0 - __bfloat162float(h0));
                    __nv_bfloat16 l1 = __float2bfloat16(v1 - __bfloat162float(h1));
                    size_t o = (size_t)row * MM + col;
                    __nv_bfloat162 hp; hp.x = h0; hp.y = h1;
                    __nv_bfloat162 lp; lp.x = l0; lp.y = l1;
                    *(__nv_bfloat162*)&outH[o] = hp;
                    *(__nv_bfloat162*)&outL[o] = lp;
                }
            }
        }
}

// ------------------------------ tiled radon --------------------------------
// Angle-adaptive smem row stride: pick s so that the per-lane address delta
// (ca - s*sa) rounds to an ODD integer -> 32 lanes hit 32 distinct banks.
#define RS_MAX   128
#define RH_MAX   95
#define SM_RADON (RH_MAX * RS_MAX * 4)   // 48640 B dynamic

__global__ __launch_bounds__(256) void radon_tiled_kernel() {
    extern __shared__ float sm[];
    __shared__ float red[256];

    int a  = blockIdx.z;
    int x0 = blockIdx.x * 64;
    int y0 = blockIdx.y * 64;
    int tid = threadIdx.x, wid = tid >> 5, lane = tid & 31;

    float ang = (float)(3.141592653589793 * (double)a / 31.0);
    float ca = cosf(ang);
    float sa = sinf(ang);
    const float cen = (float)(PP / 2);
    float c1 = cen * (ca + sa - 1.0f);
    float c2 = cen * (ca - sa - 1.0f);

    float xf0 = (float)x0, xf1 = (float)(x0 + 63);
    float yf0 = (float)y0, yf1 = (float)(y0 + 63);
    float u00 = ca * xf0 + sa * yf0 - c1, u01 = ca * xf0 + sa * yf1 - c1;
    float u10 = ca * xf1 + sa * yf0 - c1, u11 = ca * xf1 + sa * yf1 - c1;
    float v00 = -sa * xf0 + ca * yf0 - c2, v01 = -sa * xf0 + ca * yf1 - c2;
    float v10 = -sa * xf1 + ca * yf0 - c2, v11 = -sa * xf1 + ca * yf1 - c2;
    float umin = fminf(fminf(u00, u01), fminf(u10, u11));
    float umax = fmaxf(fmaxf(u00, u01), fmaxf(u10, u11));
    float vmin = fminf(fminf(v00, v01), fminf(v10, v11));
    float vmax = fmaxf(fmaxf(v00, v01), fmaxf(v10, v11));

    int u0i = (int)floorf(umin) - 1;
    int v0i = (int)floorf(vmin) - 1;
    int W = (int)floorf(umax) + 2 - u0i + 1;
    int H = (int)floorf(vmax) + 2 - v0i + 1;

    // pick conflict-free row stride (same value computed by all threads)
    int rs = W + 1;
    if (rs < 96) rs = 96;
    for (int s = rs; s < RS_MAX; ++s) {
        float d = fabsf(ca - (float)s * sa);
        int k = (int)rintf(d);
        if (k & 1) { rs = s; break; }
    }

    int u0m = u0i % PP; if (u0m < 0) u0m += PP;
    int v0m = v0i % PP; if (v0m < 0) v0m += PP;

    for (int r = wid; r < H; r += 8) {
        int rm = v0m + r; if (rm >= PP) rm -= PP;
        const float* rowp = g_pad + (size_t)rm * PP;
        for (int c = lane; c < W; c += 32) {
            int cm = u0m + c; if (cm >= PP) cm -= PP;
            sm[r * rs + c] = __ldg(rowp + cm);
        }
    }
    __syncthreads();

    int xl   = tid & 63;
    int ysub = tid >> 6;
    int x    = x0 + xl;
    float xf = (float)x;
    float bx = ca * xf - c1;
    float by = -sa * xf - c2;

    int ybeg = y0 + ysub * 16;
    float acc0 = 0.0f, acc1 = 0.0f;

#pragma unroll
    for (int i = 0; i < 16; ++i) {
        int y = ybeg + i;
        float yf  = (float)y;
        float xin = fmaf(sa, yf, bx);
        float yin = fmaf(ca, yf, by);
        float fx = floorf(xin);
        float fy = floorf(yin);
        float wx = xin - fx;
        float wy = yin - fy;
        int il = (int)fx - u0i;
        int jl = (int)fy - v0i;
        const float* p = sm + jl * rs + il;
        float s00 = p[0], s01 = p[1], s10 = p[rs], s11 = p[rs + 1];
        float top = fmaf(wx, s01 - s00, s00);
        float bot = fmaf(wx, s11 - s10, s10);
        float res = fmaf(wy, bot - top, top);
        float g = (y < PP) ? 1.0f : 0.0f;
        if (i & 1) acc1 = fmaf(g, res, acc1);
        else       acc0 = fmaf(g, res, acc0);
    }
    float acc = acc0 + acc1;

    __syncthreads();
    red[ysub * 64 + xl] = acc;
    __syncthreads();
    if (tid < 64) {
        float s = ((red[tid] + red[64 + tid]) + red[128 + tid]) + red[192 + tid];
        int xo = x0 + tid;
        if (xo < PP)
            g_lpart[(size_t)blockIdx.y * TOT + a * PP + xo] = s;
    }
}

// --------------------------- reduce / normalize ----------------------------
__global__ void reduce_max_kernel() {
    __shared__ float smax[256];
    int idx = blockIdx.x * 256 + threadIdx.x;
    float v = -__int_as_float(0x7f800000);
    if (idx < TOT) {
        float s = 0.0f;
        for (int p = 0; p < NYT; p++) s += g_lpart[(size_t)p * TOT + idx];
        g_lines[idx] = s;
        v = s;
    }
    smax[threadIdx.x] = v;
    __syncthreads();
    for (int o = 128; o > 0; o >>= 1) {
        if (threadIdx.x < o)
            smax[threadIdx.x] = fmaxf(smax[threadIdx.x], smax[threadIdx.x + o]);
        __syncthreads();
    }
    if (threadIdx.x == 0) {
        unsigned u = __float_as_uint(smax[0]);
        unsigned enc = (u & 0x80000000u) ? ~u : (u | 0x80000000u);
        atomicMax(&g_maxbits, enc);
    }
}

__global__ void normalize_kernel(float* __restrict__ out) {
    int idx = blockIdx.x * 256 + threadIdx.x;
    if (idx >= TOT) return;
    unsigned u = g_maxbits;
    float mx = (u & 0x80000000u) ? __uint_as_float(u & 0x7fffffffu)
                                 : __uint_as_float(~u);
    int x = idx >> 5;
    int a = idx & 31;
    out[idx] = g_lines[a * PP + x] / mx;
}

// ---------------------------------------------------------------------------
extern "C" void kernel_launch(void* const* d_in, const int* in_sizes, int n_in,
                              void* d_out, int out_size) {
    const float* img = (const float*)d_in[0];
    float* out = (float*)d_out;

    static int s_init = 0;
    if (!s_init) {
        cudaFuncSetAttribute(gemm_hmma_kernel<0>,
                             cudaFuncAttributeMaxDynamicSharedMemorySize, SM_GEMM);
        cudaFuncSetAttribute(gemm_hmma_kernel<1>,
                             cudaFuncAttributeMaxDynamicSharedMemorySize, SM_GEMM);
        cudaFuncSetAttribute(radon_tiled_kernel,
                             cudaFuncAttributeMaxDynamicSharedMemorySize, SM_RADON);
        s_init = 1;
    }

    init_kernel<<<(PP * PP + 255) / 256, 256>>>();
    gen_dct_kernel<<<(MM * MM + 255) / 256, 256>>>();
    transpose_split_kernel<<<dim3(64, 64), dim3(32, 8)>>>(img);

    __nv_bfloat16 *pCh, *pCl, *pXTh, *pXTl, *pTh, *pTl;
    cudaGetSymbolAddress((void**)&pCh,  g_Ch);
    cudaGetSymbolAddress((void**)&pCl,  g_Cl);
    cudaGetSymbolAddress((void**)&pXTh, g_XTh);
    cudaGetSymbolAddress((void**)&pXTl, g_XTl);
    cudaGetSymbolAddress((void**)&pTh,  g_Th);
    cudaGetSymbolAddress((void**)&pTl,  g_Tl);
    float* pPad;
    cudaGetSymbolAddress((void**)&pPad, g_pad);

    dim3 gg(MM / 128, MM / 256);
    gemm_hmma_kernel<1><<<gg, 256, SM_GEMM>>>(pCh, pCl, pXTh, pXTl,
                                              nullptr, pTh, pTl);
    gemm_hmma_kernel<0><<<gg, 256, SM_GEMM>>>(pTh, pTl, pCh, pCl,
                                              pPad, nullptr, nullptr);

    dim3 rg(NXT, NYT, NANG);
    radon_tiled_kernel<<<rg, 256, SM_RADON>>>();

    reduce_max_kernel<<<(TOT + 255) / 256, 256>>>();
    normalize_kernel<<<(TOT + 255) / 256, 256>>>(out);
}

// round 7
// speedup vs baseline: 1.0345x; 1.0345x over previous
#include <cuda_runtime.h>
#include <cuda_bf16.h>
#include <cstdint>

// ---------------------------------------------------------------------------
// image_prj: D = dct2(image) [2048x2048, ortho] -> pad to 2198x2198 ->
// 32-angle radon (bilinear, WRAP) -> lines^T / max
// GEMMs: mma.sync bf16x3 split.  Radon: smem tile + convert-free bilinear
// (magic-number floor/frac, all fixed-latency pipes, fully independent ILP).
// ---------------------------------------------------------------------------

#define MM    2048
#define PP    2198
#define PADB  75
#define NANG  32
#define TOT   (NANG * PP)
#define NYT   35
#define NXT   35

__device__ __nv_bfloat16 g_Ch[MM * MM], g_Cl[MM * MM];
__device__ __nv_bfloat16 g_XTh[MM * MM], g_XTl[MM * MM];
__device__ __nv_bfloat16 g_Th[MM * MM], g_Tl[MM * MM];
__device__ float    g_pad[PP * PP];
__device__ float    g_lpart[NYT * TOT];
__device__ float    g_lines[TOT];
__device__ unsigned g_maxbits;

// ------------------------------ PTX helpers -------------------------------
__device__ __forceinline__ uint32_t smem_u32(const void* p) {
    uint32_t a;
    asm("{ .reg .u64 t; cvta.to.shared.u64 t, %1; cvt.u32.u64 %0, t; }"
        : "=r"(a) : "l"(p));
    return a;
}
#define CP_COMMIT() asm volatile("cp.async.commit_group;" ::: "memory")
#define CP_WAIT(n)  asm volatile("cp.async.wait_group %0;" :: "n"(n) : "memory")

__device__ __forceinline__ void cp16(uint32_t dst, const void* src) {
    asm volatile("cp.async.cg.shared.global [%0], [%1], 16;"
                 :: "r"(dst), "l"(src) : "memory");
}
__device__ __forceinline__ void ldsm4(uint32_t& r0, uint32_t& r1,
                                      uint32_t& r2, uint32_t& r3, uint32_t a) {
    asm volatile("ldmatrix.sync.aligned.m8n8.x4.shared.b16 {%0,%1,%2,%3}, [%4];"
                 : "=r"(r0), "=r"(r1), "=r"(r2), "=r"(r3) : "r"(a));
}
__device__ __forceinline__ void mma16816(float* d, const uint32_t* a,
                                         const uint32_t* b) {
    asm volatile("mma.sync.aligned.m16n8k16.row.col.f32.bf16.bf16.f32 "
                 "{%0,%1,%2,%3}, {%4,%5,%6,%7}, {%8,%9}, {%0,%1,%2,%3};"
                 : "+f"(d[0]), "+f"(d[1]), "+f"(d[2]), "+f"(d[3])
                 : "r"(a[0]), "r"(a[1]), "r"(a[2]), "r"(a[3]),
                   "r"(b[0]), "r"(b[1]));
}
__device__ __forceinline__ uint32_t sw128(uint32_t b) { return b ^ ((b >> 3) & 0x70); }

// --------------------------- small prep kernels ---------------------------
__global__ void init_kernel() {
    int idx = blockIdx.x * 256 + threadIdx.x;
    if (idx < PP * PP) g_pad[idx] = 0.0f;
    if (idx == 0) g_maxbits = 0u;
}

__global__ void gen_dct_kernel() {
    int idx = blockIdx.x * 256 + threadIdx.x;
    if (idx >= MM * MM) return;
    int k = idx >> 11;
    int n = idx & (MM - 1);
    int r = ((2 * n + 1) * k) & (4 * MM - 1);
    float t = (float)r * (1.0f / (2.0f * MM));
    float c = cospif(t);
    float s = (k == 0) ? 0.022097086912079608f : 0.03125f;
    float v = s * c;
    __nv_bfloat16 h = __float2bfloat16(v);
    g_Ch[idx] = h;
    g_Cl[idx] = __float2bfloat16(v - __bfloat162float(h));
}

__global__ void transpose_split_kernel(const float* __restrict__ img) {
    __shared__ float tile[32][33];
    int bx = blockIdx.x * 32, by = blockIdx.y * 32;
    int tx = threadIdx.x, ty = threadIdx.y;
#pragma unroll
    for (int i = 0; i < 4; i++)
        tile[ty + i * 8][tx] = img[(size_t)(by + ty + i * 8) * MM + bx + tx];
    __syncthreads();
#pragma unroll
    for (int i = 0; i < 4; i++) {
        float v = tile[tx][ty + i * 8];
        __nv_bfloat16 h = __float2bfloat16(v);
        size_t o = (size_t)(bx + ty + i * 8) * MM + by + tx;
        g_XTh[o] = h;
        g_XTl[o] = __float2bfloat16(v - __bfloat162float(h));
    }
}

// ------------------------------ HMMA GEMM ---------------------------------
#define KC      64
#define NCH     (MM / KC)
#define TA      32768
#define TB      16384
#define ST_SZ   (2 * TA + 2 * TB)
#define STAGES  2
#define SM_GEMM (STAGES * ST_SZ)

__device__ __forceinline__ void load_chunk(
    uint32_t st,
    const __nv_bfloat16* __restrict__ Ah, const __nv_bfloat16* __restrict__ Al,
    const __nv_bfloat16* __restrict__ Bh, const __nv_bfloat16* __restrict__ Bl,
    int m0, int n0, int k0, int tid)
{
#pragma unroll
    for (int t = 0; t < 24; ++t) {
        int idx = tid + t * 256;
        if (idx < 4096) {
            int sp  = idx >> 11;
            int r   = (idx >> 3) & 255;
            int seg = idx & 7;
            const __nv_bfloat16* src = sp ? Al : Ah;
            cp16(st + sp * TA + sw128(r * 128 + seg * 16),
                 src + (size_t)(m0 + r) * MM + k0 + seg * 8);
        } else {
            int j   = idx - 4096;
            int sp  = j >> 10;
            int r   = (j >> 3) & 127;
            int seg = j & 7;
            const __nv_bfloat16* src = sp ? Bl : Bh;
            cp16(st + 2 * TA + sp * TB + sw128(r * 128 + seg * 16),
                 src + (size_t)(n0 + r) * MM + k0 + seg * 8);
        }
    }
}

template <int WRITEMODE>
__global__ __launch_bounds__(256, 1) void gemm_hmma_kernel(
    const __nv_bfloat16* __restrict__ Ah, const __nv_bfloat16* __restrict__ Al,
    const __nv_bfloat16* __restrict__ Bh, const __nv_bfloat16* __restrict__ Bl,
    float* __restrict__ outF, __nv_bfloat16* __restrict__ outH,
    __nv_bfloat16* __restrict__ outL)
{
    extern __shared__ char smem[];
    uint32_t sb = smem_u32(smem);
    int tid = threadIdx.x, wid = tid >> 5, lane = tid & 31;
    int m0 = blockIdx.y * 256, n0 = blockIdx.x * 128;
    int wm = wid >> 1, wn = wid & 1;

    float acc[4][8][4];
#pragma unroll
    for (int i = 0; i < 4; i++)
#pragma unroll
        for (int j = 0; j < 8; j++)
#pragma unroll
            for (int q = 0; q < 4; q++) acc[i][j][q] = 0.0f;

    int aRow  = wm * 64 + (lane & 7) + ((lane >> 3) & 1) * 8;
    int aSegB = lane >> 4;
    uint32_t aXor  = (uint32_t)(aRow & 7) << 4;
    uint32_t aBase = (uint32_t)aRow * 128;
    int bRow  = wn * 64 + (lane & 7) + ((lane >> 4) & 1) * 8;
    int bSegB = (lane >> 3) & 1;
    uint32_t bXor  = (uint32_t)(bRow & 7) << 4;
    uint32_t bBase = (uint32_t)bRow * 128;

    load_chunk(sb + 0 * ST_SZ, Ah, Al, Bh, Bl, m0, n0, 0 * KC, tid); CP_COMMIT();
    load_chunk(sb + 1 * ST_SZ, Ah, Al, Bh, Bl, m0, n0, 1 * KC, tid); CP_COMMIT();

    for (int c = 0; c < NCH; ++c) {
        if (c + 1 < NCH) CP_WAIT(1);
        else             CP_WAIT(0);
        __syncthreads();

        uint32_t st = sb + (c & 1) * ST_SZ;
        uint32_t sAh = st, sAl = st + TA, sBh = st + 2 * TA, sBl = st + 2 * TA + TB;

#pragma unroll
        for (int ks = 0; ks < 4; ++ks) {
            uint32_t aSegOff = (uint32_t)(((ks * 2 + aSegB) * 16) ^ aXor);
            uint32_t bSegOff = (uint32_t)(((ks * 2 + bSegB) * 16) ^ bXor);
            uint32_t bh[4][4], bl[4][4];
#pragma unroll
            for (int p = 0; p < 4; ++p) {
                uint32_t off = bBase + p * 2048 + bSegOff;
                ldsm4(bh[p][0], bh[p][1], bh[p][2], bh[p][3], sBh + off);
                ldsm4(bl[p][0], bl[p][1], bl[p][2], bl[p][3], sBl + off);
            }
#pragma unroll
            for (int mt = 0; mt < 4; ++mt) {
                uint32_t ah[4], al[4];
                uint32_t off = aBase + mt * 2048 + aSegOff;
                ldsm4(ah[0], ah[1], ah[2], ah[3], sAh + off);
                ldsm4(al[0], al[1], al[2], al[3], sAl + off);
#pragma unroll
                for (int nt = 0; nt < 8; ++nt) {
                    const uint32_t* pbh = &bh[nt >> 1][(nt & 1) * 2];
                    const uint32_t* pbl = &bl[nt >> 1][(nt & 1) * 2];
                    mma16816(acc[mt][nt], ah, pbh);
                    mma16816(acc[mt][nt], ah, pbl);
                    mma16816(acc[mt][nt], al, pbh);
                }
            }
        }
        __syncthreads();
        if (c + 2 < NCH)
            load_chunk(sb + (c & 1) * ST_SZ, Ah, Al, Bh, Bl,
                       m0, n0, (c + 2) * KC, tid);
        CP_COMMIT();
    }

#pragma unroll
    for (int mt = 0; mt < 4; ++mt)
#pragma unroll
        for (int nt = 0; nt < 8; ++nt) {
#pragma unroll
            for (int h = 0; h < 2; ++h) {
                int row = m0 + wm * 64 + mt * 16 + (lane >> 2) + h * 8;
                int col = n0 + wn * 64 + nt * 8 + (lane & 3) * 2;
                float v0 = acc[mt][nt][h * 2 + 0];
                float v1 = acc[mt][nt][h * 2 + 1];
                if (WRITEMODE == 0) {
                    size_t o = (size_t)(row + PADB) * PP + col + PADB;
                    outF[o]     = v0;
                    outF[o + 1] = v1;
                } else {
                    __nv_bfloat16 h0 = __float2bfloat16(v0);
                    __nv_bfloat16 h1 = __float2bfloat16(v1);
                    __nv_bfloat16 l0 = __float2bfloat16(v0 - __bfloat162float(h0));
                    __nv_bfloat16 l1 = __float2bfloat16(v1 - __bfloat162float(h1));
                    size_t o = (size_t)row * MM + col;
                    __nv_bfloat162 hp; hp.x = h0; hp.y = h1;
                    __nv_bfloat162 lp; lp.x = l0; lp.y = l1;
                    *(__nv_bfloat162*)&outH[o] = hp;
                    *(__nv_bfloat162*)&outL[o] = lp;
                }
            }
        }
}

// ------------------------------ tiled radon --------------------------------
// Static stride 97 smem tile; inner loop uses exact strip-base floor once,
// then magic-number (1.5*2^23) int/frac extraction: no F2F/F2I/floor per
// sample, every sample independent (1 fma from strip base).
#define RSW 97
#define RSH 95
#define RMAGIC 12582912.0f          // 1.5 * 2^23
#define RMAGIC_I 0x4B400000

__global__ __launch_bounds__(256) void radon_tiled_kernel() {
    __shared__ float sm[RSH * RSW];
    __shared__ float red[256];

    int a  = blockIdx.z;
    int x0 = blockIdx.x * 64;
    int y0 = blockIdx.y * 64;
    int tid = threadIdx.x, wid = tid >> 5, lane = tid & 31;

    float ang = (float)(3.141592653589793 * (double)a / 31.0);
    float ca = cosf(ang);
    float sa = sinf(ang);
    const float cen = (float)(PP / 2);
    float c1 = cen * (ca + sa - 1.0f);
    float c2 = cen * (ca - sa - 1.0f);

    float xf0 = (float)x0, xf1 = (float)(x0 + 63);
    float yf0 = (float)y0, yf1 = (float)(y0 + 63);
    float u00 = ca * xf0 + sa * yf0 - c1, u01 = ca * xf0 + sa * yf1 - c1;
    float u10 = ca * xf1 + sa * yf0 - c1, u11 = ca * xf1 + sa * yf1 - c1;
    float v00 = -sa * xf0 + ca * yf0 - c2, v01 = -sa * xf0 + ca * yf1 - c2;
    float v10 = -sa * xf1 + ca * yf0 - c2, v11 = -sa * xf1 + ca * yf1 - c2;
    float umin = fminf(fminf(u00, u01), fminf(u10, u11));
    float umax = fmaxf(fmaxf(u00, u01), fmaxf(u10, u11));
    float vmin = fminf(fminf(v00, v01), fminf(v10, v11));
    float vmax = fmaxf(fmaxf(v00, v01), fmaxf(v10, v11));

    int u0i = (int)floorf(umin) - 1;
    int v0i = (int)floorf(vmin) - 1;
    int W = (int)floorf(umax) + 2 - u0i + 1;
    int H = (int)floorf(vmax) + 2 - v0i + 1;

    int u0m = u0i % PP; if (u0m < 0) u0m += PP;
    int v0m = v0i % PP; if (v0m < 0) v0m += PP;

    for (int r = wid; r < H; r += 8) {
        int rm = v0m + r; if (rm >= PP) rm -= PP;
        const float* rowp = g_pad + (size_t)rm * PP;
        for (int c = lane; c < W; c += 32) {
            int cm = u0m + c; if (cm >= PP) cm -= PP;
            sm[r * RSW + c] = __ldg(rowp + cm);
        }
    }
    __syncthreads();

    int xl   = tid & 63;
    int ysub = tid >> 6;
    int x    = x0 + xl;
    float xf = (float)x;
    float bx = ca * xf - c1;
    float by = -sa * xf - c2;

    int ybeg = y0 + ysub * 16;
    // exact strip base (same math as validated per-sample version)
    float ybf  = (float)ybeg;
    float xin0 = fmaf(sa, ybf, bx);
    float yin0 = fmaf(ca, ybf, by);
    float fx0 = floorf(xin0);
    float fy0 = floorf(yin0);
    float wx0 = xin0 - fx0;
    float wy0 = yin0 - fy0;
    int   base0 = ((int)fy0 - v0i) * RSW + ((int)fx0 - u0i);

    float acc0 = 0.0f, acc1 = 0.0f;
#pragma unroll
    for (int i = 0; i < 16; ++i) {
        float tx = fmaf((float)i, sa, wx0);       // [0, 17)
        float ty = fmaf((float)i, ca, wy0);       // (-16, 17)
        float ux = tx + RMAGIC;
        float uy = ty + RMAGIC;
        int nx = __float_as_int(ux) - RMAGIC_I;   // round(tx)
        int ny = __float_as_int(uy) - RMAGIC_I;   // round(ty)
        float wx = tx - (ux - RMAGIC);            // in [-0.5, 0.5]
        float wy = ty - (uy - RMAGIC);
        if (wx < 0.0f) { wx += 1.0f; nx -= 1; }
        if (wy < 0.0f) { wy += 1.0f; ny -= 1; }
        const float* p = sm + (base0 + ny * RSW + nx);
        float s00 = p[0], s01 = p[1], s10 = p[RSW], s11 = p[RSW + 1];
        float top = fmaf(wx, s01 - s00, s00);
        float bot = fmaf(wx, s11 - s10, s10);
        float res = fmaf(wy, bot - top, top);
        float g = (ybeg + i < PP) ? 1.0f : 0.0f;
        if (i & 1) acc1 = fmaf(g, res, acc1);
        else       acc0 = fmaf(g, res, acc0);
    }
    float acc = acc0 + acc1;

    __syncthreads();
    red[ysub * 64 + xl] = acc;
    __syncthreads();
    if (tid < 64) {
        float s = ((red[tid] + red[64 + tid]) + red[128 + tid]) + red[192 + tid];
        int xo = x0 + tid;
        if (xo < PP)
            g_lpart[(size_t)blockIdx.y * TOT + a * PP + xo] = s;
    }
}

// --------------------------- reduce / normalize ----------------------------
__global__ void reduce_max_kernel() {
    __shared__ float smax[256];
    int idx = blockIdx.x * 256 + threadIdx.x;
    float v = -__int_as_float(0x7f800000);
    if (idx < TOT) {
        float s = 0.0f;
        for (int p = 0; p < NYT; p++) s += g_lpart[(size_t)p * TOT + idx];
        g_lines[idx] = s;
        v = s;
    }
    smax[threadIdx.x] = v;
    __syncthreads();
    for (int o = 128; o > 0; o >>= 1) {
        if (threadIdx.x < o)
            smax[threadIdx.x] = fmaxf(smax[threadIdx.x], smax[threadIdx.x + o]);
        __syncthreads();
    }
    if (threadIdx.x == 0) {
        unsigned u = __float_as_uint(smax[0]);
        unsigned enc = (u & 0x80000000u) ? ~u : (u | 0x80000000u);
        atomicMax(&g_maxbits, enc);
    }
}

__global__ void normalize_kernel(float* __restrict__ out) {
    int idx = blockIdx.x * 256 + threadIdx.x;
    if (idx >= TOT) return;
    unsigned u = g_maxbits;
    float mx = (u & 0x80000000u) ? __uint_as_float(u & 0x7fffffffu)
                                 : __uint_as_float(~u);
    int x = idx >> 5;
    int a = idx & 31;
    out[idx] = g_lines[a * PP + x] / mx;
}

// ---------------------------------------------------------------------------
extern "C" void kernel_launch(void* const* d_in, const int* in_sizes, int n_in,
                              void* d_out, int out_size) {
    const float* img = (const float*)d_in[0];
    float* out = (float*)d_out;

    static int s_init = 0;
    if (!s_init) {
        cudaFuncSetAttribute(gemm_hmma_kernel<0>,
                             cudaFuncAttributeMaxDynamicSharedMemorySize, SM_GEMM);
        cudaFuncSetAttribute(gemm_hmma_kernel<1>,
                             cudaFuncAttributeMaxDynamicSharedMemorySize, SM_GEMM);
        s_init = 1;
    }

    init_kernel<<<(PP * PP + 255) / 256, 256>>>();
    gen_dct_kernel<<<(MM * MM + 255) / 256, 256>>>();
    transpose_split_kernel<<<dim3(64, 64), dim3(32, 8)>>>(img);

    __nv_bfloat16 *pCh, *pCl, *pXTh, *pXTl, *pTh, *pTl;
    cudaGetSymbolAddress((void**)&pCh,  g_Ch);
    cudaGetSymbolAddress((void**)&pCl,  g_Cl);
    cudaGetSymbolAddress((void**)&pXTh, g_XTh);
    cudaGetSymbolAddress((void**)&pXTl, g_XTl);
    cudaGetSymbolAddress((void**)&pTh,  g_Th);
    cudaGetSymbolAddress((void**)&pTl,  g_Tl);
    float* pPad;
    cudaGetSymbolAddress((void**)&pPad, g_pad);

    dim3 gg(MM / 128, MM / 256);
    gemm_hmma_kernel<1><<<gg, 256, SM_GEMM>>>(pCh, pCl, pXTh, pXTl,
                                              nullptr, pTh, pTl);
    gemm_hmma_kernel<0><<<gg, 256, SM_GEMM>>>(pTh, pTl, pCh, pCl,
                                              pPad, nullptr, nullptr);

    dim3 rg(NXT, NYT, NANG);
    radon_tiled_kernel<<<rg, 256>>>();

    reduce_max_kernel<<<(TOT + 255) / 256, 256>>>();
    normalize_kernel<<<(TOT + 255) / 256, 256>>>(out);
}

// round 8
// speedup vs baseline: 1.1097x; 1.0727x over previous
#include <cuda_runtime.h>
#include <cuda_bf16.h>
#include <cstdint>

// ---------------------------------------------------------------------------
// image_prj: D = dct2(image) [2048x2048, ortho] -> pad to 2198x2198 ->
// 32-angle radon (bilinear, WRAP) -> lines^T / max
// GEMMs: mma.sync bf16x3 split.  Radon: cp.async footprint staging +
// convert-free bilinear sampling.
// ---------------------------------------------------------------------------

#define MM    2048
#define PP    2198
#define PADB  75
#define NANG  32
#define TOT   (NANG * PP)
#define NYT   35
#define NXT   35

__device__ __nv_bfloat16 g_Ch[MM * MM], g_Cl[MM * MM];
__device__ __nv_bfloat16 g_XTh[MM * MM], g_XTl[MM * MM];
__device__ __nv_bfloat16 g_Th[MM * MM], g_Tl[MM * MM];
__device__ float    g_pad[PP * PP];
__device__ float    g_lpart[NYT * TOT];
__device__ float    g_lines[TOT];
__device__ unsigned g_maxbits;

// ------------------------------ PTX helpers -------------------------------
__device__ __forceinline__ uint32_t smem_u32(const void* p) {
    uint32_t a;
    asm("{ .reg .u64 t; cvta.to.shared.u64 t, %1; cvt.u32.u64 %0, t; }"
        : "=r"(a) : "l"(p));
    return a;
}
#define CP_COMMIT() asm volatile("cp.async.commit_group;" ::: "memory")
#define CP_WAIT(n)  asm volatile("cp.async.wait_group %0;" :: "n"(n) : "memory")

__device__ __forceinline__ void cp16(uint32_t dst, const void* src) {
    asm volatile("cp.async.cg.shared.global [%0], [%1], 16;"
                 :: "r"(dst), "l"(src) : "memory");
}
__device__ __forceinline__ void cp4(uint32_t dst, const void* src) {
    asm volatile("cp.async.ca.shared.global [%0], [%1], 4;"
                 :: "r"(dst), "l"(src) : "memory");
}
__device__ __forceinline__ void ldsm4(uint32_t& r0, uint32_t& r1,
                                      uint32_t& r2, uint32_t& r3, uint32_t a) {
    asm volatile("ldmatrix.sync.aligned.m8n8.x4.shared.b16 {%0,%1,%2,%3}, [%4];"
                 : "=r"(r0), "=r"(r1), "=r"(r2), "=r"(r3) : "r"(a));
}
__device__ __forceinline__ void mma16816(float* d, const uint32_t* a,
                                         const uint32_t* b) {
    asm volatile("mma.sync.aligned.m16n8k16.row.col.f32.bf16.bf16.f32 "
                 "{%0,%1,%2,%3}, {%4,%5,%6,%7}, {%8,%9}, {%0,%1,%2,%3};"
                 : "+f"(d[0]), "+f"(d[1]), "+f"(d[2]), "+f"(d[3])
                 : "r"(a[0]), "r"(a[1]), "r"(a[2]), "r"(a[3]),
                   "r"(b[0]), "r"(b[1]));
}
__device__ __forceinline__ uint32_t sw128(uint32_t b) { return b ^ ((b >> 3) & 0x70); }

// --------------------------- small prep kernels ---------------------------
// zero only the pad border (interior is fully overwritten by gemm2)
#define NB1 (150 * PP)            // top 75 + bottom 75 rows
#define NB2 (MM * 150)            // left/right 75 cols of middle rows
__global__ void init_border_kernel() {
    int idx = blockIdx.x * 256 + threadIdx.x;
    if (idx == 0) g_maxbits = 0u;
    if (idx < NB1) {
        int r = idx / PP, c = idx % PP;
        int row = (r < 75) ? r : (2123 + r - 75);
        g_pad[(size_t)row * PP + c] = 0.0f;
    } else if (idx < NB1 + NB2) {
        int j = idx - NB1;
        int r = j / 150, c = j % 150;
        int col = (c < 75) ? c : (2123 + c - 75);
        g_pad[(size_t)(75 + r) * PP + col] = 0.0f;
    }
}

__global__ void gen_dct_kernel() {
    int idx = blockIdx.x * 256 + threadIdx.x;
    if (idx >= MM * MM) return;
    int k = idx >> 11;
    int n = idx & (MM - 1);
    int r = ((2 * n + 1) * k) & (4 * MM - 1);
    float t = (float)r * (1.0f / (2.0f * MM));
    float c = cospif(t);
    float s = (k == 0) ? 0.022097086912079608f : 0.03125f;
    float v = s * c;
    __nv_bfloat16 h = __float2bfloat16(v);
    g_Ch[idx] = h;
    g_Cl[idx] = __float2bfloat16(v - __bfloat162float(h));
}

__global__ void transpose_split_kernel(const float* __restrict__ img) {
    __shared__ float tile[32][33];
    int bx = blockIdx.x * 32, by = blockIdx.y * 32;
    int tx = threadIdx.x, ty = threadIdx.y;
#pragma unroll
    for (int i = 0; i < 4; i++)
        tile[ty + i * 8][tx] = img[(size_t)(by + ty + i * 8) * MM + bx + tx];
    __syncthreads();
#pragma unroll
    for (int i = 0; i < 4; i++) {
        float v = tile[tx][ty + i * 8];
        __nv_bfloat16 h = __float2bfloat16(v);
        size_t o = (size_t)(bx + ty + i * 8) * MM + by + tx;
        g_XTh[o] = h;
        g_XTl[o] = __float2bfloat16(v - __bfloat162float(h));
    }
}

// ------------------------------ HMMA GEMM ---------------------------------
#define KC      64
#define NCH     (MM / KC)
#define TA      32768
#define TB      16384
#define ST_SZ   (2 * TA + 2 * TB)
#define STAGES  2
#define SM_GEMM (STAGES * ST_SZ)

__device__ __forceinline__ void load_chunk(
    uint32_t st,
    const __nv_bfloat16* __restrict__ Ah, const __nv_bfloat16* __restrict__ Al,
    const __nv_bfloat16* __restrict__ Bh, const __nv_bfloat16* __restrict__ Bl,
    int m0, int n0, int k0, int tid)
{
#pragma unroll
    for (int t = 0; t < 24; ++t) {
        int idx = tid + t * 256;
        if (idx < 4096) {
            int sp  = idx >> 11;
            int r   = (idx >> 3) & 255;
            int seg = idx & 7;
            const __nv_bfloat16* src = sp ? Al : Ah;
            cp16(st + sp * TA + sw128(r * 128 + seg * 16),
                 src + (size_t)(m0 + r) * MM + k0 + seg * 8);
        } else {
            int j   = idx - 4096;
            int sp  = j >> 10;
            int r   = (j >> 3) & 127;
            int seg = j & 7;
            const __nv_bfloat16* src = sp ? Bl : Bh;
            cp16(st + 2 * TA + sp * TB + sw128(r * 128 + seg * 16),
                 src + (size_t)(n0 + r) * MM + k0 + seg * 8);
        }
    }
}

template <int WRITEMODE>
__global__ __launch_bounds__(256, 1) void gemm_hmma_kernel(
    const __nv_bfloat16* __restrict__ Ah, const __nv_bfloat16* __restrict__ Al,
    const __nv_bfloat16* __restrict__ Bh, const __nv_bfloat16* __restrict__ Bl,
    float* __restrict__ outF, __nv_bfloat16* __restrict__ outH,
    __nv_bfloat16* __restrict__ outL)
{
    extern __shared__ char smem[];
    uint32_t sb = smem_u32(smem);
    int tid = threadIdx.x, wid = tid >> 5, lane = tid & 31;
    int m0 = blockIdx.y * 256, n0 = blockIdx.x * 128;
    int wm = wid >> 1, wn = wid & 1;

    float acc[4][8][4];
#pragma unroll
    for (int i = 0; i < 4; i++)
#pragma unroll
        for (int j = 0; j < 8; j++)
#pragma unroll
            for (int q = 0; q < 4; q++) acc[i][j][q] = 0.0f;

    int aRow  = wm * 64 + (lane & 7) + ((lane >> 3) & 1) * 8;
    int aSegB = lane >> 4;
    uint32_t aXor  = (uint32_t)(aRow & 7) << 4;
    uint32_t aBase = (uint32_t)aRow * 128;
    int bRow  = wn * 64 + (lane & 7) + ((lane >> 4) & 1) * 8;
    int bSegB = (lane >> 3) & 1;
    uint32_t bXor  = (uint32_t)(bRow & 7) << 4;
    uint32_t bBase = (uint32_t)bRow * 128;

    load_chunk(sb + 0 * ST_SZ, Ah, Al, Bh, Bl, m0, n0, 0 * KC, tid); CP_COMMIT();
    load_chunk(sb + 1 * ST_SZ, Ah, Al, Bh, Bl, m0, n0, 1 * KC, tid); CP_COMMIT();

    for (int c = 0; c < NCH; ++c) {
        if (c + 1 < NCH) CP_WAIT(1);
        else             CP_WAIT(0);
        __syncthreads();

        uint32_t st = sb + (c & 1) * ST_SZ;
        uint32_t sAh = st, sAl = st + TA, sBh = st + 2 * TA, sBl = st + 2 * TA + TB;

#pragma unroll
        for (int ks = 0; ks < 4; ++ks) {
            uint32_t aSegOff = (uint32_t)(((ks * 2 + aSegB) * 16) ^ aXor);
            uint32_t bSegOff = (uint32_t)(((ks * 2 + bSegB) * 16) ^ bXor);
            uint32_t bh[4][4], bl[4][4];
#pragma unroll
            for (int p = 0; p < 4; ++p) {
                uint32_t off = bBase + p * 2048 + bSegOff;
                ldsm4(bh[p][0], bh[p][1], bh[p][2], bh[p][3], sBh + off);
                ldsm4(bl[p][0], bl[p][1], bl[p][2], bl[p][3], sBl + off);
            }
#pragma unroll
            for (int mt = 0; mt < 4; ++mt) {
                uint32_t ah[4], al[4];
                uint32_t off = aBase + mt * 2048 + aSegOff;
                ldsm4(ah[0], ah[1], ah[2], ah[3], sAh + off);
                ldsm4(al[0], al[1], al[2], al[3], sAl + off);
#pragma unroll
                for (int nt = 0; nt < 8; ++nt) {
                    const uint32_t* pbh = &bh[nt >> 1][(nt & 1) * 2];
                    const uint32_t* pbl = &bl[nt >> 1][(nt & 1) * 2];
                    mma16816(acc[mt][nt], ah, pbh);
                    mma16816(acc[mt][nt], ah, pbl);
                    mma16816(acc[mt][nt], al, pbh);
                }
            }
        }
        __syncthreads();
        if (c + 2 < NCH)
            load_chunk(sb + (c & 1) * ST_SZ, Ah, Al, Bh, Bl,
                       m0, n0, (c + 2) * KC, tid);
        CP_COMMIT();
    }

#pragma unroll
    for (int mt = 0; mt < 4; ++mt)
#pragma unroll
        for (int nt = 0; nt < 8; ++nt) {
#pragma unroll
            for (int h = 0; h < 2; ++h) {
                int row = m0 + wm * 64 + mt * 16 + (lane >> 2) + h * 8;
                int col = n0 + wn * 64 + nt * 8 + (lane & 3) * 2;
                float v0 = acc[mt][nt][h * 2 + 0];
                float v1 = acc[mt][nt][h * 2 + 1];
                if (WRITEMODE == 0) {
                    size_t o = (size_t)(row + PADB) * PP + col + PADB;
                    outF[o]     = v0;
                    outF[o + 1] = v1;
                } else {
                    __nv_bfloat16 h0 = __float2bfloat16(v0);
                    __nv_bfloat16 h1 = __float2bfloat16(v1);
                    __nv_bfloat16 l0 = __float2bfloat16(v0 - __bfloat162float(h0));
                    __nv_bfloat16 l1 = __float2bfloat16(v1 - __bfloat162float(h1));
                    size_t o = (size_t)row * MM + col;
                    __nv_bfloat162 hp; hp.x = h0; hp.y = h1;
                    __nv_bfloat162 lp; lp.x = l0; lp.y = l1;
                    *(__nv_bfloat162*)&outH[o] = hp;
                    *(__nv_bfloat162*)&outL[o] = lp;
                }
            }
        }
}

// ------------------------------ tiled radon --------------------------------
// Footprint staged via cp.async (fire-and-forget: no LDG->STS serialization).
// Sampling: strip-base floor once, magic-number int/frac per sample.
#define RSW 97
#define RSH 95
#define RMAGIC 12582912.0f          // 1.5 * 2^23
#define RMAGIC_I 0x4B400000

__global__ __launch_bounds__(256) void radon_tiled_kernel() {
    __shared__ float sm[RSH * RSW];
    __shared__ float red[256];

    int a  = blockIdx.z;
    int x0 = blockIdx.x * 64;
    int y0 = blockIdx.y * 64;
    int tid = threadIdx.x, wid = tid >> 5, lane = tid & 31;

    float ang = (float)(3.141592653589793 * (double)a / 31.0);
    float ca = cosf(ang);
    float sa = sinf(ang);
    const float cen = (float)(PP / 2);
    float c1 = cen * (ca + sa - 1.0f);
    float c2 = cen * (ca - sa - 1.0f);

    float xf0 = (float)x0, xf1 = (float)(x0 + 63);
    float yf0 = (float)y0, yf1 = (float)(y0 + 63);
    float u00 = ca * xf0 + sa * yf0 - c1, u01 = ca * xf0 + sa * yf1 - c1;
    float u10 = ca * xf1 + sa * yf0 - c1, u11 = ca * xf1 + sa * yf1 - c1;
    float v00 = -sa * xf0 + ca * yf0 - c2, v01 = -sa * xf0 + ca * yf1 - c2;
    float v10 = -sa * xf1 + ca * yf0 - c2, v11 = -sa * xf1 + ca * yf1 - c2;
    float umin = fminf(fminf(u00, u01), fminf(u10, u11));
    float umax = fmaxf(fmaxf(u00, u01), fmaxf(u10, u11));
    float vmin = fminf(fminf(v00, v01), fminf(v10, v11));
    float vmax = fmaxf(fmaxf(v00, v01), fmaxf(v10, v11));

    int u0i = (int)floorf(umin) - 1;
    int v0i = (int)floorf(vmin) - 1;
    int W = (int)floorf(umax) + 2 - u0i + 1;
    int H = (int)floorf(vmax) + 2 - v0i + 1;

    int u0m = u0i % PP; if (u0m < 0) u0m += PP;
    int v0m = v0i % PP; if (v0m < 0) v0m += PP;

    // footprint via cp.async: per-thread 4B copies, all in flight at once
    uint32_t smb = smem_u32(sm);
    for (int r = wid; r < H; r += 8) {
        int rm = v0m + r; if (rm >= PP) rm -= PP;
        const float* rowp = g_pad + (size_t)rm * PP;
        uint32_t drow = smb + (uint32_t)(r * RSW) * 4;
        for (int c = lane; c < W; c += 32) {
            int cm = u0m + c; if (cm >= PP) cm -= PP;
            cp4(drow + (uint32_t)c * 4, rowp + cm);
        }
    }
    CP_COMMIT();

    // per-thread constants while copies fly
    int xl   = tid & 63;
    int ysub = tid >> 6;
    int x    = x0 + xl;
    float xf = (float)x;
    float bx = ca * xf - c1;
    float by = -sa * xf - c2;

    int ybeg = y0 + ysub * 16;
    float ybf  = (float)ybeg;
    float xin0 = fmaf(sa, ybf, bx);
    float yin0 = fmaf(ca, ybf, by);
    float fx0 = floorf(xin0);
    float fy0 = floorf(yin0);
    float wx0 = xin0 - fx0;
    float wy0 = yin0 - fy0;
    int   base0 = ((int)fy0 - v0i) * RSW + ((int)fx0 - u0i);

    CP_WAIT(0);
    __syncthreads();

    float acc0 = 0.0f, acc1 = 0.0f;
#pragma unroll
    for (int i = 0; i < 16; ++i) {
        float tx = fmaf((float)i, sa, wx0);
        float ty = fmaf((float)i, ca, wy0);
        float ux = tx + RMAGIC;
        float uy = ty + RMAGIC;
        int nx = __float_as_int(ux) - RMAGIC_I;
        int ny = __float_as_int(uy) - RMAGIC_I;
        float wx = tx - (ux - RMAGIC);
        float wy = ty - (uy - RMAGIC);
        if (wx < 0.0f) { wx += 1.0f; nx -= 1; }
        if (wy < 0.0f) { wy += 1.0f; ny -= 1; }
        const float* p = sm + (base0 + ny * RSW + nx);
        float s00 = p[0], s01 = p[1], s10 = p[RSW], s11 = p[RSW + 1];
        float top = fmaf(wx, s01 - s00, s00);
        float bot = fmaf(wx, s11 - s10, s10);
        float res = fmaf(wy, bot - top, top);
        float g = (ybeg + i < PP) ? 1.0f : 0.0f;
        if (i & 1) acc1 = fmaf(g, res, acc1);
        else       acc0 = fmaf(g, res, acc0);
    }
    float acc = acc0 + acc1;

    __syncthreads();
    red[ysub * 64 + xl] = acc;
    __syncthreads();
    if (tid < 64) {
        float s = ((red[tid] + red[64 + tid]) + red[128 + tid]) + red[192 + tid];
        int xo = x0 + tid;
        if (xo < PP)
            g_lpart[(size_t)blockIdx.y * TOT + a * PP + xo] = s;
    }
}

// --------------------------- reduce / normalize ----------------------------
__global__ void reduce_max_kernel() {
    __shared__ float smax[256];
    int idx = blockIdx.x * 256 + threadIdx.x;
    float v = -__int_as_float(0x7f800000);
    if (idx < TOT) {
        float s = 0.0f;
        for (int p = 0; p < NYT; p++) s += g_lpart[(size_t)p * TOT + idx];
        g_lines[idx] = s;
        v = s;
    }
    smax[threadIdx.x] = v;
    __syncthreads();
    for (int o = 128; o > 0; o >>= 1) {
        if (threadIdx.x < o)
            smax[threadIdx.x] = fmaxf(smax[threadIdx.x], smax[threadIdx.x + o]);
        __syncthreads();
    }
    if (threadIdx.x == 0) {
        unsigned u = __float_as_uint(smax[0]);
        unsigned enc = (u & 0x80000000u) ? ~u : (u | 0x80000000u);
        atomicMax(&g_maxbits, enc);
    }
}

__global__ void normalize_kernel(float* __restrict__ out) {
    int idx = blockIdx.x * 256 + threadIdx.x;
    if (idx >= TOT) return;
    unsigned u = g_maxbits;
    float mx = (u & 0x80000000u) ? __uint_as_float(u & 0x7fffffffu)
                                 : __uint_as_float(~u);
    int x = idx >> 5;
    int a = idx & 31;
    out[idx] = g_lines[a * PP + x] / mx;
}

// ---------------------------------------------------------------------------
extern "C" void kernel_launch(void* const* d_in, const int* in_sizes, int n_in,
                              void* d_out, int out_size) {
    const float* img = (const float*)d_in[0];
    float* out = (float*)d_out;

    static int s_init = 0;
    if (!s_init) {
        cudaFuncSetAttribute(gemm_hmma_kernel<0>,
                             cudaFuncAttributeMaxDynamicSharedMemorySize, SM_GEMM);
        cudaFuncSetAttribute(gemm_hmma_kernel<1>,
                             cudaFuncAttributeMaxDynamicSharedMemorySize, SM_GEMM);
        s_init = 1;
    }

    init_border_kernel<<<(NB1 + NB2 + 255) / 256, 256>>>();
    gen_dct_kernel<<<(MM * MM + 255) / 256, 256>>>();
    transpose_split_kernel<<<dim3(64, 64), dim3(32, 8)>>>(img);

    __nv_bfloat16 *pCh, *pCl, *pXTh, *pXTl, *pTh, *pTl;
    cudaGetSymbolAddress((void**)&pCh,  g_Ch);
    cudaGetSymbolAddress((void**)&pCl,  g_Cl);
    cudaGetSymbolAddress((void**)&pXTh, g_XTh);
    cudaGetSymbolAddress((void**)&pXTl, g_XTl);
    cudaGetSymbolAddress((void**)&pTh,  g_Th);
    cudaGetSymbolAddress((void**)&pTl,  g_Tl);
    float* pPad;
    cudaGetSymbolAddress((void**)&pPad, g_pad);

    dim3 gg(MM / 128, MM / 256);
    gemm_hmma_kernel<1><<<gg, 256, SM_GEMM>>>(pCh, pCl, pXTh, pXTl,
                                              nullptr, pTh, pTl);
    gemm_hmma_kernel<0><<<gg, 256, SM_GEMM>>>(pTh, pTl, pCh, pCl,
                                              pPad, nullptr, nullptr);

    dim3 rg(NXT, NYT, NANG);
    radon_tiled_kernel<<<rg, 256>>>();

    reduce_max_kernel<<<(TOT + 255) / 256, 256>>>();
    normalize_kernel<<<(TOT + 255) / 256, 256>>>(out);
}

// round 9
// speedup vs baseline: 1.2643x; 1.1393x over previous
#include <cuda_runtime.h>
#include <cuda_bf16.h>
#include <cstdint>

// ---------------------------------------------------------------------------
// image_prj: D = dct2(image) [2048x2048, ortho] -> pad to 2198x2198 ->
// 32-angle radon (bilinear, WRAP) -> lines^T / max
// GEMMs: mma.sync bf16x3 split.  Radon: 16B cp.async footprint staging
// (row-stride-2200 padded image for alignment) + convert-free bilinear.
// ---------------------------------------------------------------------------

#define MM    2048
#define PP    2198
#define PPS   2200               // padded row stride (16B-aligned rows)
#define PADB  75
#define NANG  32
#define TOT   (NANG * PP)
#define NYT   35
#define NXT   35

__device__ __nv_bfloat16 g_Ch[MM * MM], g_Cl[MM * MM];
__device__ __nv_bfloat16 g_XTh[MM * MM], g_XTl[MM * MM];
__device__ __nv_bfloat16 g_Th[MM * MM], g_Tl[MM * MM];
__device__ float    g_pad[PP * PPS];
__device__ float    g_lpart[NYT * TOT];
__device__ float    g_lines[TOT];
__device__ unsigned g_maxbits;

// ------------------------------ PTX helpers -------------------------------
__device__ __forceinline__ uint32_t smem_u32(const void* p) {
    uint32_t a;
    asm("{ .reg .u64 t; cvta.to.shared.u64 t, %1; cvt.u32.u64 %0, t; }"
        : "=r"(a) : "l"(p));
    return a;
}
#define CP_COMMIT() asm volatile("cp.async.commit_group;" ::: "memory")
#define CP_WAIT(n)  asm volatile("cp.async.wait_group %0;" :: "n"(n) : "memory")

__device__ __forceinline__ void cp16(uint32_t dst, const void* src) {
    asm volatile("cp.async.cg.shared.global [%0], [%1], 16;"
                 :: "r"(dst), "l"(src) : "memory");
}
__device__ __forceinline__ void cp4(uint32_t dst, const void* src) {
    asm volatile("cp.async.ca.shared.global [%0], [%1], 4;"
                 :: "r"(dst), "l"(src) : "memory");
}
__device__ __forceinline__ void ldsm4(uint32_t& r0, uint32_t& r1,
                                      uint32_t& r2, uint32_t& r3, uint32_t a) {
    asm volatile("ldmatrix.sync.aligned.m8n8.x4.shared.b16 {%0,%1,%2,%3}, [%4];"
                 : "=r"(r0), "=r"(r1), "=r"(r2), "=r"(r3) : "r"(a));
}
__device__ __forceinline__ void mma16816(float* d, const uint32_t* a,
                                         const uint32_t* b) {
    asm volatile("mma.sync.aligned.m16n8k16.row.col.f32.bf16.bf16.f32 "
                 "{%0,%1,%2,%3}, {%4,%5,%6,%7}, {%8,%9}, {%0,%1,%2,%3};"
                 : "+f"(d[0]), "+f"(d[1]), "+f"(d[2]), "+f"(d[3])
                 : "r"(a[0]), "r"(a[1]), "r"(a[2]), "r"(a[3]),
                   "r"(b[0]), "r"(b[1]));
}
__device__ __forceinline__ uint32_t sw128(uint32_t b) { return b ^ ((b >> 3) & 0x70); }

// --------------------------- small prep kernels ---------------------------
#define NB1 (150 * PP)
#define NB2 (MM * 150)
__global__ void init_border_kernel() {
    int idx = blockIdx.x * 256 + threadIdx.x;
    if (idx == 0) g_maxbits = 0u;
    if (idx < NB1) {
        int r = idx / PP, c = idx % PP;
        int row = (r < 75) ? r : (2123 + r - 75);
        g_pad[(size_t)row * PPS + c] = 0.0f;
    } else if (idx < NB1 + NB2) {
        int j = idx - NB1;
        int r = j / 150, c = j % 150;
        int col = (c < 75) ? c : (2123 + c - 75);
        g_pad[(size_t)(75 + r) * PPS + col] = 0.0f;
    }
}

__global__ void gen_dct_kernel() {
    int idx = blockIdx.x * 256 + threadIdx.x;
    if (idx >= MM * MM) return;
    int k = idx >> 11;
    int n = idx & (MM - 1);
    int r = ((2 * n + 1) * k) & (4 * MM - 1);
    float t = (float)r * (1.0f / (2.0f * MM));
    float c = cospif(t);
    float s = (k == 0) ? 0.022097086912079608f : 0.03125f;
    float v = s * c;
    __nv_bfloat16 h = __float2bfloat16(v);
    g_Ch[idx] = h;
    g_Cl[idx] = __float2bfloat16(v - __bfloat162float(h));
}

__global__ void transpose_split_kernel(const float* __restrict__ img) {
    __shared__ float tile[32][33];
    int bx = blockIdx.x * 32, by = blockIdx.y * 32;
    int tx = threadIdx.x, ty = threadIdx.y;
#pragma unroll
    for (int i = 0; i < 4; i++)
        tile[ty + i * 8][tx] = img[(size_t)(by + ty + i * 8) * MM + bx + tx];
    __syncthreads();
#pragma unroll
    for (int i = 0; i < 4; i++) {
        float v = tile[tx][ty + i * 8];
        __nv_bfloat16 h = __float2bfloat16(v);
        size_t o = (size_t)(bx + ty + i * 8) * MM + by + tx;
        g_XTh[o] = h;
        g_XTl[o] = __float2bfloat16(v - __bfloat162float(h));
    }
}

// ------------------------------ HMMA GEMM ---------------------------------
#define KC      64
#define NCH     (MM / KC)
#define TA      32768
#define TB      16384
#define ST_SZ   (2 * TA + 2 * TB)
#define STAGES  2
#define SM_GEMM (STAGES * ST_SZ)

__device__ __forceinline__ void load_chunk(
    uint32_t st,
    const __nv_bfloat16* __restrict__ Ah, const __nv_bfloat16* __restrict__ Al,
    const __nv_bfloat16* __restrict__ Bh, const __nv_bfloat16* __restrict__ Bl,
    int m0, int n0, int k0, int tid)
{
#pragma unroll
    for (int t = 0; t < 24; ++t) {
        int idx = tid + t * 256;
        if (idx < 4096) {
            int sp  = idx >> 11;
            int r   = (idx >> 3) & 255;
            int seg = idx & 7;
            const __nv_bfloat16* src = sp ? Al : Ah;
            cp16(st + sp * TA + sw128(r * 128 + seg * 16),
                 src + (size_t)(m0 + r) * MM + k0 + seg * 8);
        } else {
            int j   = idx - 4096;
            int sp  = j >> 10;
            int r   = (j >> 3) & 127;
            int seg = j & 7;
            const __nv_bfloat16* src = sp ? Bl : Bh;
            cp16(st + 2 * TA + sp * TB + sw128(r * 128 + seg * 16),
                 src + (size_t)(n0 + r) * MM + k0 + seg * 8);
        }
    }
}

template <int WRITEMODE>
__global__ __launch_bounds__(256, 1) void gemm_hmma_kernel(
    const __nv_bfloat16* __restrict__ Ah, const __nv_bfloat16* __restrict__ Al,
    const __nv_bfloat16* __restrict__ Bh, const __nv_bfloat16* __restrict__ Bl,
    float* __restrict__ outF, __nv_bfloat16* __restrict__ outH,
    __nv_bfloat16* __restrict__ outL)
{
    extern __shared__ char smem[];
    uint32_t sb = smem_u32(smem);
    int tid = threadIdx.x, wid = tid >> 5, lane = tid & 31;
    int m0 = blockIdx.y * 256, n0 = blockIdx.x * 128;
    int wm = wid >> 1, wn = wid & 1;

    float acc[4][8][4];
#pragma unroll
    for (int i = 0; i < 4; i++)
#pragma unroll
        for (int j = 0; j < 8; j++)
#pragma unroll
            for (int q = 0; q < 4; q++) acc[i][j][q] = 0.0f;

    int aRow  = wm * 64 + (lane & 7) + ((lane >> 3) & 1) * 8;
    int aSegB = lane >> 4;
    uint32_t aXor  = (uint32_t)(aRow & 7) << 4;
    uint32_t aBase = (uint32_t)aRow * 128;
    int bRow  = wn * 64 + (lane & 7) + ((lane >> 4) & 1) * 8;
    int bSegB = (lane >> 3) & 1;
    uint32_t bXor  = (uint32_t)(bRow & 7) << 4;
    uint32_t bBase = (uint32_t)bRow * 128;

    load_chunk(sb + 0 * ST_SZ, Ah, Al, Bh, Bl, m0, n0, 0 * KC, tid); CP_COMMIT();
    load_chunk(sb + 1 * ST_SZ, Ah, Al, Bh, Bl, m0, n0, 1 * KC, tid); CP_COMMIT();

    for (int c = 0; c < NCH; ++c) {
        if (c + 1 < NCH) CP_WAIT(1);
        else             CP_WAIT(0);
        __syncthreads();

        uint32_t st = sb + (c & 1) * ST_SZ;
        uint32_t sAh = st, sAl = st + TA, sBh = st + 2 * TA, sBl = st + 2 * TA + TB;

#pragma unroll
        for (int ks = 0; ks < 4; ++ks) {
            uint32_t aSegOff = (uint32_t)(((ks * 2 + aSegB) * 16) ^ aXor);
            uint32_t bSegOff = (uint32_t)(((ks * 2 + bSegB) * 16) ^ bXor);
            uint32_t bh[4][4], bl[4][4];
#pragma unroll
            for (int p = 0; p < 4; ++p) {
                uint32_t off = bBase + p * 2048 + bSegOff;
                ldsm4(bh[p][0], bh[p][1], bh[p][2], bh[p][3], sBh + off);
                ldsm4(bl[p][0], bl[p][1], bl[p][2], bl[p][3], sBl + off);
            }
#pragma unroll
            for (int mt = 0; mt < 4; ++mt) {
                uint32_t ah[4], al[4];
                uint32_t off = aBase + mt * 2048 + aSegOff;
                ldsm4(ah[0], ah[1], ah[2], ah[3], sAh + off);
                ldsm4(al[0], al[1], al[2], al[3], sAl + off);
#pragma unroll
                for (int nt = 0; nt < 8; ++nt) {
                    const uint32_t* pbh = &bh[nt >> 1][(nt & 1) * 2];
                    const uint32_t* pbl = &bl[nt >> 1][(nt & 1) * 2];
                    mma16816(acc[mt][nt], ah, pbh);
                    mma16816(acc[mt][nt], ah, pbl);
                    mma16816(acc[mt][nt], al, pbh);
                }
            }
        }
        __syncthreads();
        if (c + 2 < NCH)
            load_chunk(sb + (c & 1) * ST_SZ, Ah, Al, Bh, Bl,
                       m0, n0, (c + 2) * KC, tid);
        CP_COMMIT();
    }

#pragma unroll
    for (int mt = 0; mt < 4; ++mt)
#pragma unroll
        for (int nt = 0; nt < 8; ++nt) {
#pragma unroll
            for (int h = 0; h < 2; ++h) {
                int row = m0 + wm * 64 + mt * 16 + (lane >> 2) + h * 8;
                int col = n0 + wn * 64 + nt * 8 + (lane & 3) * 2;
                float v0 = acc[mt][nt][h * 2 + 0];
                float v1 = acc[mt][nt][h * 2 + 1];
                if (WRITEMODE == 0) {
                    size_t o = (size_t)(row + PADB) * PPS + col + PADB;
                    outF[o]     = v0;
                    outF[o + 1] = v1;
                } else {
                    __nv_bfloat16 h0 = __float2bfloat16(v0);
                    __nv_bfloat16 h1 = __float2bfloat16(v1);
                    __nv_bfloat16 l0 = __float2bfloat16(v0 - __bfloat162float(h0));
                    __nv_bfloat16 l1 = __float2bfloat16(v1 - __bfloat162float(h1));
                    size_t o = (size_t)row * MM + col;
                    __nv_bfloat162 hp; hp.x = h0; hp.y = h1;
                    __nv_bfloat162 lp; lp.x = l0; lp.y = l1;
                    *(__nv_bfloat162*)&outH[o] = hp;
                    *(__nv_bfloat162*)&outL[o] = lp;
                }
            }
        }
}

// ------------------------------ tiled radon --------------------------------
// Footprint x-origin aligned down to 4 floats; fast path = one 16B cp.async
// per 4 floats (rows 16B-aligned thanks to PPS=2200); slow path (x-wrap) cp4.
#define RSW 100                  // smem row stride, multiple of 4
#define RSH 95
#define RMAGIC 12582912.0f       // 1.5 * 2^23
#define RMAGIC_I 0x4B400000

__global__ __launch_bounds__(256) void radon_tiled_kernel() {
    __shared__ float sm[RSH * RSW];
    __shared__ float red[256];

    int a  = blockIdx.z;
    int x0 = blockIdx.x * 64;
    int y0 = blockIdx.y * 64;
    int tid = threadIdx.x, wid = tid >> 5, lane = tid & 31;

    float ang = (float)(3.141592653589793 * (double)a / 31.0);
    float ca = cosf(ang);
    float sa = sinf(ang);
    const float cen = (float)(PP / 2);
    float c1 = cen * (ca + sa - 1.0f);
    float c2 = cen * (ca - sa - 1.0f);

    float xf0 = (float)x0, xf1 = (float)(x0 + 63);
    float yf0 = (float)y0, yf1 = (float)(y0 + 63);
    float u00 = ca * xf0 + sa * yf0 - c1, u01 = ca * xf0 + sa * yf1 - c1;
    float u10 = ca * xf1 + sa * yf0 - c1, u11 = ca * xf1 + sa * yf1 - c1;
    float v00 = -sa * xf0 + ca * yf0 - c2, v01 = -sa * xf0 + ca * yf1 - c2;
    float v10 = -sa * xf1 + ca * yf0 - c2, v11 = -sa * xf1 + ca * yf1 - c2;
    float umin = fminf(fminf(u00, u01), fminf(u10, u11));
    float umax = fmaxf(fmaxf(u00, u01), fmaxf(u10, u11));
    float vmin = fminf(fminf(v00, v01), fminf(v10, v11));
    float vmax = fmaxf(fmaxf(v00, v01), fmaxf(v10, v11));

    int u0i = (int)floorf(umin) - 1;
    int v0i = (int)floorf(vmin) - 1;
    int W = (int)floorf(umax) + 2 - u0i + 1;
    int H = (int)floorf(vmax) + 2 - v0i + 1;

    int u0m = u0i % PP; if (u0m < 0) u0m += PP;
    int v0m = v0i % PP; if (v0m < 0) v0m += PP;

    // shift origin down to 4-float alignment
    int sft  = u0m & 3;
    int u0s  = u0i - sft;            // logical origin of smem column 0
    int u0ms = u0m - sft;            // aligned start in [0, PP)
    int W4   = (W + sft + 3) & ~3;

    uint32_t smb = smem_u32(sm);
    if (u0ms + W4 <= PP) {
        // fast path: contiguous aligned rows, 16B copies
        int nq = W4 >> 2;
        for (int r = wid; r < H; r += 8) {
            int rm = v0m + r; if (rm >= PP) rm -= PP;
            const float* src = g_pad + (size_t)rm * PPS + u0ms;
            uint32_t drow = smb + (uint32_t)(r * RSW) * 4;
            for (int q = lane; q < nq; q += 32)
                cp16(drow + (uint32_t)q * 16, src + q * 4);
        }
    } else {
        // slow path: x-wrap, scalar copies
        for (int r = wid; r < H; r += 8) {
            int rm = v0m + r; if (rm >= PP) rm -= PP;
            const float* rowp = g_pad + (size_t)rm * PPS;
            uint32_t drow = smb + (uint32_t)(r * RSW) * 4;
            for (int c = lane; c < W4; c += 32) {
                int cm = u0ms + c; if (cm >= PP) cm -= PP;
                cp4(drow + (uint32_t)c * 4, rowp + cm);
            }
        }
    }
    CP_COMMIT();

    // per-thread constants while copies fly
    int xl   = tid & 63;
    int ysub = tid >> 6;
    int x    = x0 + xl;
    float xf = (float)x;
    float bx = ca * xf - c1;
    float by = -sa * xf - c2;

    int ybeg = y0 + ysub * 16;
    float ybf  = (float)ybeg;
    float xin0 = fmaf(sa, ybf, bx);
    float yin0 = fmaf(ca, ybf, by);
    float fx0 = floorf(xin0);
    float fy0 = floorf(yin0);
    float wx0 = xin0 - fx0;
    float wy0 = yin0 - fy0;
    int   base0 = ((int)fy0 - v0i) * RSW + ((int)fx0 - u0s);

    CP_WAIT(0);
    __syncthreads();

    float acc0 = 0.0f, acc1 = 0.0f;
#pragma unroll
    for (int i = 0; i < 16; ++i) {
        float tx = fmaf((float)i, sa, wx0);
        float ty = fmaf((float)i, ca, wy0);
        float ux = tx + RMAGIC;
        float uy = ty + RMAGIC;
        int nx = __float_as_int(ux) - RMAGIC_I;
        int ny = __float_as_int(uy) - RMAGIC_I;
        float wx = tx - (ux - RMAGIC);
        float wy = ty - (uy - RMAGIC);
        if (wx < 0.0f) { wx += 1.0f; nx -= 1; }
        if (wy < 0.0f) { wy += 1.0f; ny -= 1; }
        const float* p = sm + (base0 + ny * RSW + nx);
        float s00 = p[0], s01 = p[1], s10 = p[RSW], s11 = p[RSW + 1];
        float top = fmaf(wx, s01 - s00, s00);
        float bot = fmaf(wx, s11 - s10, s10);
        float res = fmaf(wy, bot - top, top);
        float g = (ybeg + i < PP) ? 1.0f : 0.0f;
        if (i & 1) acc1 = fmaf(g, res, acc1);
        else       acc0 = fmaf(g, res, acc0);
    }
    float acc = acc0 + acc1;

    __syncthreads();
    red[ysub * 64 + xl] = acc;
    __syncthreads();
    if (tid < 64) {
        float s = ((red[tid] + red[64 + tid]) + red[128 + tid]) + red[192 + tid];
        int xo = x0 + tid;
        if (xo < PP)
            g_lpart[(size_t)blockIdx.y * TOT + a * PP + xo] = s;
    }
}

// --------------------------- reduce / normalize ----------------------------
__global__ void reduce_max_kernel() {
    __shared__ float smax[256];
    int idx = blockIdx.x * 256 + threadIdx.x;
    float v = -__int_as_float(0x7f800000);
    if (idx < TOT) {
        float s = 0.0f;
        for (int p = 0; p < NYT; p++) s += g_lpart[(size_t)p * TOT + idx];
        g_lines[idx] = s;
        v = s;
    }
    smax[threadIdx.x] = v;
    __syncthreads();
    for (int o = 128; o > 0; o >>= 1) {
        if (threadIdx.x < o)
            smax[threadIdx.x] = fmaxf(smax[threadIdx.x], smax[threadIdx.x + o]);
        __syncthreads();
    }
    if (threadIdx.x == 0) {
        unsigned u = __float_as_uint(smax[0]);
        unsigned enc = (u & 0x80000000u) ? ~u : (u | 0x80000000u);
        atomicMax(&g_maxbits, enc);
    }
}

__global__ void normalize_kernel(float* __restrict__ out) {
    int idx = blockIdx.x * 256 + threadIdx.x;
    if (idx >= TOT) return;
    unsigned u = g_maxbits;
    float mx = (u & 0x80000000u) ? __uint_as_float(u & 0x7fffffffu)
                                 : __uint_as_float(~u);
    int x = idx >> 5;
    int a = idx & 31;
    out[idx] = g_lines[a * PP + x] / mx;
}

// ---------------------------------------------------------------------------
extern "C" void kernel_launch(void* const* d_in, const int* in_sizes, int n_in,
                              void* d_out, int out_size) {
    const float* img = (const float*)d_in[0];
    float* out = (float*)d_out;

    static int s_init = 0;
    if (!s_init) {
        cudaFuncSetAttribute(gemm_hmma_kernel<0>,
                             cudaFuncAttributeMaxDynamicSharedMemorySize, SM_GEMM);
        cudaFuncSetAttribute(gemm_hmma_kernel<1>,
                             cudaFuncAttributeMaxDynamicSharedMemorySize, SM_GEMM);
        s_init = 1;
    }

    init_border_kernel<<<(NB1 + NB2 + 255) / 256, 256>>>();
    gen_dct_kernel<<<(MM * MM + 255) / 256, 256>>>();
    transpose_split_kernel<<<dim3(64, 64), dim3(32, 8)>>>(img);

    __nv_bfloat16 *pCh, *pCl, *pXTh, *pXTl, *pTh, *pTl;
    cudaGetSymbolAddress((void**)&pCh,  g_Ch);
    cudaGetSymbolAddress((void**)&pCl,  g_Cl);
    cudaGetSymbolAddress((void**)&pXTh, g_XTh);
    cudaGetSymbolAddress((void**)&pXTl, g_XTl);
    cudaGetSymbolAddress((void**)&pTh,  g_Th);
    cudaGetSymbolAddress((void**)&pTl,  g_Tl);
    float* pPad;
    cudaGetSymbolAddress((void**)&pPad, g_pad);

    dim3 gg(MM / 128, MM / 256);
    gemm_hmma_kernel<1><<<gg, 256, SM_GEMM>>>(pCh, pCl, pXTh, pXTl,
                                              nullptr, pTh, pTl);
    gemm_hmma_kernel<0><<<gg, 256, SM_GEMM>>>(pTh, pTl, pCh, pCl,
                                              pPad, nullptr, nullptr);

    dim3 rg(NXT, NYT, NANG);
    radon_tiled_kernel<<<rg, 256>>>();

    reduce_max_kernel<<<(TOT + 255) / 256, 256>>>();
    normalize_kernel<<<(TOT + 255) / 256, 256>>>(out);
}